// round 3
// baseline (speedup 1.0000x reference)
#include <cuda_runtime.h>
#include <math.h>
#include <stdint.h>

#define B     64
#define NSUB  4
#define PP    128
#define TP    512
#define DD    256
#define HH    256
#define FEAT  131072
#define M1    128
#define NROWS (B*TP)            // 32768
#define KCHUNKS 128             // FEAT / 1024

#define SA_STR 36               // 32 + 4 pad
#define SB_STR 136              // 128 + 8 pad (8t+g conflict-free frag loads)

// ---------------- scratch (device globals; no allocation) ----------------
__device__ float g_invn[B*TP];
__device__ float g_dinv[B*TP];
__device__ float g_A[(size_t)B*NSUB*PP*PP];        // 16.8 MB raw A blocks (diag=1)
__device__ float g_XW[(size_t)B*TP*HH];            // 33.5 MB
__device__ float g_Hb[(size_t)B*TP*HH];            // 33.5 MB (pre-BN h)
__device__ float g_sum[HH], g_sumsq[HH], g_scale[HH], g_shift[HH];
__device__ float g_Z1part[(size_t)KCHUNKS*B*M1];   // 4 MB split-K partials
__device__ float g_z1[B*M1];

// ---------------- tf32 helpers (3xTF32 split for ~fp32 accuracy) ----------------
__device__ __forceinline__ float tf32r(float x) {
    uint32_t u;
    asm("cvt.rna.tf32.f32 %0, %1;" : "=r"(u) : "f"(x));
    return __uint_as_float(u);
}
#define F2U(x) __float_as_uint(x)
__device__ __forceinline__ void split1(float v, uint32_t& h, uint32_t& l) {
    float hf = tf32r(v);
    h = F2U(hf);
    l = F2U(tf32r(v - hf));
}
__device__ __forceinline__ void mma8(float* c, const uint32_t* a, const uint32_t* b) {
    asm volatile("mma.sync.aligned.m16n8k8.row.col.f32.tf32.tf32.f32 "
                 "{%0,%1,%2,%3}, {%4,%5,%6,%7}, {%8,%9}, {%0,%1,%2,%3};\n"
                 : "+f"(c[0]), "+f"(c[1]), "+f"(c[2]), "+f"(c[3])
                 : "r"(a[0]), "r"(a[1]), "r"(a[2]), "r"(a[3]),
                   "r"(b[0]), "r"(b[1]));
}

// ---------------- 1/||x_row|| (exact fp32) ----------------
__global__ void k_invn(const float* __restrict__ x) {
    int row  = blockIdx.x * 8 + (threadIdx.x >> 5);
    int lane = threadIdx.x & 31;
    const float* xr = x + (size_t)row * DD;
    float s = 0.f;
#pragma unroll
    for (int i = 0; i < 8; i++) { float v = xr[lane + 32*i]; s += v*v; }
#pragma unroll
    for (int o = 16; o; o >>= 1) s += __shfl_xor_sync(0xffffffffu, s, o);
    if (lane == 0) g_invn[row] = 1.0f / fmaxf(sqrtf(s), 1e-12f);
}

// ---------------- per-(b,n): A = (cos+1)/2 * mask, diag=1; dinv ----------------
__global__ void __launch_bounds__(256) k_simA(const float* __restrict__ x,
                                              const float* __restrict__ mask) {
    __shared__ float sX[128*SA_STR];
    __shared__ float sInv[128];
    __shared__ float sdeg[128];
    int bn = blockIdx.x;
    int b = bn >> 2, n = bn & 3;
    const float* Xb = x + ((size_t)b*TP + n*PP) * DD;
    int tid = threadIdx.x, w = tid >> 5, lane = tid & 31, g = lane >> 2, t = lane & 3;
    int wm = w & 3, wn = w >> 2;
    if (tid < 128) { sInv[tid] = g_invn[b*TP + n*PP + tid]; sdeg[tid] = 0.f; }

    float acc[2][8][4];
#pragma unroll
    for (int mi=0;mi<2;mi++)
#pragma unroll
        for (int ni=0;ni<8;ni++)
#pragma unroll
            for (int q=0;q<4;q++) acc[mi][ni][q] = 0.f;

    for (int k0 = 0; k0 < DD; k0 += 32) {
        __syncthreads();
#pragma unroll
        for (int it = 0; it < 4; it++) {
            int idx = tid + it*256;
            int r = idx >> 3, q = (idx & 7) * 4;
            float4 v = *(const float4*)(Xb + (size_t)r*DD + k0 + q);
            *(float4*)&sX[r*SA_STR+q] = v;
        }
        __syncthreads();
#pragma unroll
        for (int kk = 0; kk < 32; kk += 8) {
            uint32_t ah[2][4], al[2][4];
#pragma unroll
            for (int mi=0;mi<2;mi++) {
                int rb = wm*32 + mi*16;
                split1(sX[(rb+g  )*SA_STR + kk+t  ], ah[mi][0], al[mi][0]);
                split1(sX[(rb+g+8)*SA_STR + kk+t  ], ah[mi][1], al[mi][1]);
                split1(sX[(rb+g  )*SA_STR + kk+t+4], ah[mi][2], al[mi][2]);
                split1(sX[(rb+g+8)*SA_STR + kk+t+4], ah[mi][3], al[mi][3]);
            }
#pragma unroll
            for (int ni=0;ni<8;ni++) {
                int cb = wn*64 + ni*8 + g;
                uint32_t bh[2], bl[2];
                split1(sX[cb*SA_STR + kk+t  ], bh[0], bl[0]);
                split1(sX[cb*SA_STR + kk+t+4], bh[1], bl[1]);
#pragma unroll
                for (int mi=0;mi<2;mi++) {
                    mma8(acc[mi][ni], al[mi], bh);
                    mma8(acc[mi][ni], ah[mi], bl);
                    mma8(acc[mi][ni], ah[mi], bh);
                }
            }
        }
    }
    __syncthreads();

    float* Ab = g_A + (size_t)bn * (PP*PP);
#pragma unroll
    for (int ni=0;ni<8;ni++) {
        int c0 = wn*64 + ni*8 + 2*t, c1 = c0 + 1;
        float ic0 = sInv[c0], ic1 = sInv[c1];
        float cs0 = 0.f, cs1 = 0.f;
#pragma unroll
        for (int mi=0;mi<2;mi++) {
            int r0 = wm*32 + mi*16 + g, r1 = r0 + 8;
            float i0 = sInv[r0], i1 = sInv[r1];
            float v00 = (r0==c0) ? 1.f : (acc[mi][ni][0]*i0*ic0 + 1.f)*0.5f*mask[r0*PP+c0];
            float v01 = (r0==c1) ? 1.f : (acc[mi][ni][1]*i0*ic1 + 1.f)*0.5f*mask[r0*PP+c1];
            float v10 = (r1==c0) ? 1.f : (acc[mi][ni][2]*i1*ic0 + 1.f)*0.5f*mask[r1*PP+c0];
            float v11 = (r1==c1) ? 1.f : (acc[mi][ni][3]*i1*ic1 + 1.f)*0.5f*mask[r1*PP+c1];
            *(float2*)&Ab[r0*PP + c0] = make_float2(v00, v01);
            *(float2*)&Ab[r1*PP + c0] = make_float2(v10, v11);
            atomicAdd(&sdeg[r0], v00 + v01);
            atomicAdd(&sdeg[r1], v10 + v11);
            (void)cs0; (void)cs1;
        }
    }
    __syncthreads();
    if (tid < 128) {
        float deg = sdeg[tid];
        g_dinv[b*TP + n*PP + tid] = (deg > 0.f) ? rsqrtf(fmaxf(deg, 1e-12f)) : 0.f;
    }
}

// ---------------- [32768,256] @ [256,256] + bias -> g_XW (3xTF32) ----------------
// bn=1: input A holds raw pre-BN h; apply relu(v*g_scale[c]+g_shift[c]) on load.
__global__ void __launch_bounds__(256) k_xw(const float* __restrict__ A,
                                            const float* __restrict__ W,
                                            const float* __restrict__ bias,
                                            int bn) {
    __shared__ float sA[128*SA_STR];
    __shared__ float sB[32*SB_STR];
    __shared__ float sSc[256], sSh[256];
    int tid = threadIdx.x, w = tid >> 5, lane = tid & 31, g = lane >> 2, t = lane & 3;
    int wm = w & 3, wn = w >> 2;
    int m0 = blockIdx.y * 128, n0 = blockIdx.x * 128;
    if (bn) { sSc[tid] = g_scale[tid]; sSh[tid] = g_shift[tid]; }
    float acc[2][8][4];
#pragma unroll
    for (int mi=0;mi<2;mi++)
#pragma unroll
        for (int ni=0;ni<8;ni++)
#pragma unroll
            for (int q=0;q<4;q++) acc[mi][ni][q] = 0.f;

    for (int k0 = 0; k0 < 256; k0 += 32) {
        __syncthreads();
#pragma unroll
        for (int it = 0; it < 4; it++) {
            int idx = tid + it*256;
            int r = idx >> 3, q = (idx & 7) * 4;
            float4 v = *(const float4*)(A + (size_t)(m0+r)*256 + k0 + q);
            if (bn) {
                int c = k0 + q;
                v.x = fmaxf(fmaf(v.x, sSc[c],   sSh[c]),   0.f);
                v.y = fmaxf(fmaf(v.y, sSc[c+1], sSh[c+1]), 0.f);
                v.z = fmaxf(fmaf(v.z, sSc[c+2], sSh[c+2]), 0.f);
                v.w = fmaxf(fmaf(v.w, sSc[c+3], sSh[c+3]), 0.f);
            }
            *(float4*)&sA[r*SA_STR+q] = v;
        }
#pragma unroll
        for (int it = 0; it < 4; it++) {
            int idx = tid + it*256;
            int r = idx >> 5, q = (idx & 31) * 4;
            float4 v = *(const float4*)(W + (size_t)(k0+r)*256 + n0 + q);
            *(float4*)&sB[r*SB_STR+q] = v;
        }
        __syncthreads();
#pragma unroll
        for (int kk = 0; kk < 32; kk += 8) {
            uint32_t ah[2][4], al[2][4];
#pragma unroll
            for (int mi=0;mi<2;mi++) {
                int rb = wm*32 + mi*16;
                split1(sA[(rb+g  )*SA_STR + kk+t  ], ah[mi][0], al[mi][0]);
                split1(sA[(rb+g+8)*SA_STR + kk+t  ], ah[mi][1], al[mi][1]);
                split1(sA[(rb+g  )*SA_STR + kk+t+4], ah[mi][2], al[mi][2]);
                split1(sA[(rb+g+8)*SA_STR + kk+t+4], ah[mi][3], al[mi][3]);
            }
#pragma unroll
            for (int ni=0;ni<8;ni++) {
                int cb = wn*64 + ni*8 + g;
                uint32_t bh[2], bl[2];
                split1(sB[(kk+t  )*SB_STR + cb], bh[0], bl[0]);
                split1(sB[(kk+t+4)*SB_STR + cb], bh[1], bl[1]);
#pragma unroll
                for (int mi=0;mi<2;mi++) {
                    mma8(acc[mi][ni], al[mi], bh);
                    mma8(acc[mi][ni], ah[mi], bl);
                    mma8(acc[mi][ni], ah[mi], bh);
                }
            }
        }
    }
#pragma unroll
    for (int mi=0;mi<2;mi++) {
        int r0 = m0 + wm*32 + mi*16 + g, r1 = r0 + 8;
#pragma unroll
        for (int ni=0;ni<8;ni++) {
            int c0 = n0 + wn*64 + ni*8 + 2*t;
            float b0 = bias[c0], b1 = bias[c0+1];
            *(float2*)&g_XW[(size_t)r0*256 + c0] = make_float2(acc[mi][ni][0] + b0, acc[mi][ni][1] + b1);
            *(float2*)&g_XW[(size_t)r1*256 + c0] = make_float2(acc[mi][ni][2] + b0, acc[mi][ni][3] + b1);
        }
    }
}

// ---------------- H = dinv_i * A(b,n) @ (dinv_j * XW) (3xTF32) + fused BN stats ----------------
__global__ void __launch_bounds__(256) k_bmm() {
    __shared__ float sA[128*SA_STR];
    __shared__ float sB[32*SB_STR];
    __shared__ float sDv[128];
    __shared__ float sSum[128], sSq[128];
    int bn = blockIdx.y;
    int b = bn >> 2, n = bn & 3;
    int h0 = blockIdx.x * 128;
    const float* Ab    = g_A + (size_t)bn * (PP*PP);
    const float* Xrows = g_XW + ((size_t)(b*TP + n*PP)) * HH;
    int tid = threadIdx.x, w = tid >> 5, lane = tid & 31, g = lane >> 2, t = lane & 3;
    int wm = w & 3, wn = w >> 2;
    if (tid < 128) { sDv[tid] = g_dinv[b*TP + n*PP + tid]; sSum[tid] = 0.f; sSq[tid] = 0.f; }

    float acc[2][8][4];
#pragma unroll
    for (int mi=0;mi<2;mi++)
#pragma unroll
        for (int ni=0;ni<8;ni++)
#pragma unroll
            for (int q=0;q<4;q++) acc[mi][ni][q] = 0.f;

    for (int k0 = 0; k0 < PP; k0 += 32) {
        __syncthreads();
#pragma unroll
        for (int it = 0; it < 4; it++) {
            int idx = tid + it*256;
            int r = idx >> 3, q = (idx & 7) * 4;
            float4 v = *(const float4*)(Ab + (size_t)r*PP + k0 + q);
            *(float4*)&sA[r*SA_STR+q] = v;
        }
#pragma unroll
        for (int it = 0; it < 4; it++) {
            int idx = tid + it*256;
            int r = idx >> 5, q = (idx & 31) * 4;
            float dv = sDv[k0+r];
            float4 v = *(const float4*)(Xrows + (size_t)(k0+r)*HH + h0 + q);
            v.x *= dv; v.y *= dv; v.z *= dv; v.w *= dv;
            *(float4*)&sB[r*SB_STR+q] = v;
        }
        __syncthreads();
#pragma unroll
        for (int kk = 0; kk < 32; kk += 8) {
            uint32_t ah[2][4], al[2][4];
#pragma unroll
            for (int mi=0;mi<2;mi++) {
                int rb = wm*32 + mi*16;
                split1(sA[(rb+g  )*SA_STR + kk+t  ], ah[mi][0], al[mi][0]);
                split1(sA[(rb+g+8)*SA_STR + kk+t  ], ah[mi][1], al[mi][1]);
                split1(sA[(rb+g  )*SA_STR + kk+t+4], ah[mi][2], al[mi][2]);
                split1(sA[(rb+g+8)*SA_STR + kk+t+4], ah[mi][3], al[mi][3]);
            }
#pragma unroll
            for (int ni=0;ni<8;ni++) {
                int cb = wn*64 + ni*8 + g;
                uint32_t bh[2], bl[2];
                split1(sB[(kk+t  )*SB_STR + cb], bh[0], bl[0]);
                split1(sB[(kk+t+4)*SB_STR + cb], bh[1], bl[1]);
#pragma unroll
                for (int mi=0;mi<2;mi++) {
                    mma8(acc[mi][ni], al[mi], bh);
                    mma8(acc[mi][ni], ah[mi], bl);
                    mma8(acc[mi][ni], ah[mi], bh);
                }
            }
        }
    }
    float* base = g_Hb + ((size_t)(b*TP + n*PP)) * HH;
#pragma unroll
    for (int ni=0;ni<8;ni++) {
        int cl = wn*64 + ni*8 + 2*t;
        float cs0 = 0.f, cs1 = 0.f, cq0 = 0.f, cq1 = 0.f;
#pragma unroll
        for (int mi=0;mi<2;mi++) {
            int r0 = wm*32 + mi*16 + g, r1 = r0 + 8;
            float d0 = sDv[r0], d1 = sDv[r1];
            float v00 = acc[mi][ni][0]*d0, v01 = acc[mi][ni][1]*d0;
            float v10 = acc[mi][ni][2]*d1, v11 = acc[mi][ni][3]*d1;
            *(float2*)&base[(size_t)r0*HH + h0 + cl] = make_float2(v00, v01);
            *(float2*)&base[(size_t)r1*HH + h0 + cl] = make_float2(v10, v11);
            cs0 += v00 + v10; cs1 += v01 + v11;
            cq0 += v00*v00 + v10*v10; cq1 += v01*v01 + v11*v11;
        }
        atomicAdd(&sSum[cl],   cs0);
        atomicAdd(&sSum[cl+1], cs1);
        atomicAdd(&sSq[cl],    cq0);
        atomicAdd(&sSq[cl+1],  cq1);
    }
    __syncthreads();
    if (tid < 128) {
        atomicAdd(&g_sum[h0 + tid],   sSum[tid]);
        atomicAdd(&g_sumsq[h0 + tid], sSq[tid]);
    }
}

// ---------------- BN finalize ----------------
__global__ void k_zero() { g_sum[threadIdx.x] = 0.f; g_sumsq[threadIdx.x] = 0.f; }

__global__ void k_bnfin(const float* __restrict__ g, const float* __restrict__ be) {
    int c = threadIdx.x;
    const float invn = 1.0f / (float)NROWS;
    float m = g_sum[c] * invn;
    float v = g_sumsq[c] * invn - m*m;
    float sc = g[c] * rsqrtf(v + 1e-5f);
    g_scale[c] = sc;
    g_shift[c] = be[c] - m*sc;
}

// ---------------- split-K readout GEMM (3xTF32), BN2+relu fused on load ----------------
__global__ void __launch_bounds__(256) k_mlp1(const float* __restrict__ Wm1) {
    __shared__ float sG[64*SA_STR];
    __shared__ float sW[32*SB_STR];
    __shared__ float sSc[256], sSh[256];
    int kc = blockIdx.x;
    int kbase = kc * 1024;
    int tid = threadIdx.x, w = tid >> 5, lane = tid & 31, g = lane >> 2, t = lane & 3;
    int wm = w & 3, wn = w >> 2;
    sSc[tid] = g_scale[tid]; sSh[tid] = g_shift[tid];
    float acc[8][4];
#pragma unroll
    for (int ni=0;ni<8;ni++)
#pragma unroll
        for (int q=0;q<4;q++) acc[ni][q] = 0.f;

    for (int k0 = 0; k0 < 1024; k0 += 32) {
        __syncthreads();
#pragma unroll
        for (int it = 0; it < 2; it++) {
            int idx = tid + it*256;
            int r = idx >> 3, q = (idx & 7) * 4;
            int c = (k0 + q) & 255;
            float4 v = *(const float4*)(g_Hb + (size_t)r*FEAT + kbase + k0 + q);
            v.x = fmaxf(fmaf(v.x, sSc[c],   sSh[c]),   0.f);
            v.y = fmaxf(fmaf(v.y, sSc[c+1], sSh[c+1]), 0.f);
            v.z = fmaxf(fmaf(v.z, sSc[c+2], sSh[c+2]), 0.f);
            v.w = fmaxf(fmaf(v.w, sSc[c+3], sSh[c+3]), 0.f);
            *(float4*)&sG[r*SA_STR+q] = v;
        }
#pragma unroll
        for (int it = 0; it < 4; it++) {
            int idx = tid + it*256;
            int r = idx >> 5, q = (idx & 31) * 4;
            float4 v = *(const float4*)(Wm1 + (size_t)(kbase + k0 + r)*128 + q);
            *(float4*)&sW[r*SB_STR+q] = v;
        }
        __syncthreads();
#pragma unroll
        for (int kk = 0; kk < 32; kk += 8) {
            uint32_t ah[4], al[4];
            int rb = wm*16;
            split1(sG[(rb+g  )*SA_STR + kk+t  ], ah[0], al[0]);
            split1(sG[(rb+g+8)*SA_STR + kk+t  ], ah[1], al[1]);
            split1(sG[(rb+g  )*SA_STR + kk+t+4], ah[2], al[2]);
            split1(sG[(rb+g+8)*SA_STR + kk+t+4], ah[3], al[3]);
#pragma unroll
            for (int ni=0;ni<8;ni++) {
                int cb = wn*64 + ni*8 + g;
                uint32_t bh[2], bl[2];
                split1(sW[(kk+t  )*SB_STR + cb], bh[0], bl[0]);
                split1(sW[(kk+t+4)*SB_STR + cb], bh[1], bl[1]);
                mma8(acc[ni], al, bh);
                mma8(acc[ni], ah, bl);
                mma8(acc[ni], ah, bh);
            }
        }
    }
    float* out = g_Z1part + (size_t)kc * (B*M1);
    int r0 = wm*16 + g, r1 = r0 + 8;
#pragma unroll
    for (int ni=0;ni<8;ni++) {
        int c0 = wn*64 + ni*8 + 2*t;
        *(float2*)&out[r0*M1 + c0] = make_float2(acc[ni][0], acc[ni][1]);
        *(float2*)&out[r1*M1 + c0] = make_float2(acc[ni][2], acc[ni][3]);
    }
}

__global__ void k_red(const float* __restrict__ bm1) {
    int o = blockIdx.x*256 + threadIdx.x;   // 0..8191
    float s = bm1[o & 127];
    for (int kc = 0; kc < KCHUNKS; kc++) s += g_Z1part[(size_t)kc*(B*M1) + o];
    g_z1[o] = s;
}

// ---------------- head: bn1d+relu, z@Wm2, bn1d+relu, z@Wm3 ----------------
__global__ void __launch_bounds__(256) k_head(const float* __restrict__ gm1, const float* __restrict__ bem1,
                                              const float* __restrict__ Wm2, const float* __restrict__ bm2,
                                              const float* __restrict__ gm2, const float* __restrict__ bem2,
                                              const float* __restrict__ Wm3, const float* __restrict__ bm3,
                                              float* __restrict__ out) {
    __shared__ float sz1[64][128];
    __shared__ float sz2[64][64];
    int tid = threadIdx.x;

    if (tid < 128) {
        float s = 0.f, s2 = 0.f;
        for (int b = 0; b < 64; b++) { float v = g_z1[b*128 + tid]; s += v; s2 += v*v; }
        float m = s * (1.f/64.f), var = s2 * (1.f/64.f) - m*m;
        float sc = gm1[tid] * rsqrtf(var + 1e-5f);
        float sh = bem1[tid] - m*sc;
        for (int b = 0; b < 64; b++)
            sz1[b][tid] = fmaxf(fmaf(g_z1[b*128 + tid], sc, sh), 0.f);
    }
    __syncthreads();

    for (int o = tid; o < 4096; o += 256) {
        int b = o >> 6, j = o & 63;
        float s = bm2[j];
#pragma unroll 8
        for (int m = 0; m < 128; m++) s = fmaf(sz1[b][m], Wm2[m*64 + j], s);
        sz2[b][j] = s;
    }
    __syncthreads();

    if (tid < 64) {
        float s = 0.f, s2 = 0.f;
        for (int b = 0; b < 64; b++) { float v = sz2[b][tid]; s += v; s2 += v*v; }
        float m = s * (1.f/64.f), var = s2 * (1.f/64.f) - m*m;
        float sc = gm2[tid] * rsqrtf(var + 1e-5f);
        float sh = bem2[tid] - m*sc;
        for (int b = 0; b < 64; b++)
            sz2[b][tid] = fmaxf(fmaf(sz2[b][tid], sc, sh), 0.f);
    }
    __syncthreads();

    if (tid < 128) {
        int b = tid >> 1, c = tid & 1;
        float s = bm3[c];
#pragma unroll
        for (int j = 0; j < 64; j++) s = fmaf(sz2[b][j], Wm3[j*2 + c], s);
        out[b*2 + c] = s;
    }
}

// ---------------- launch ----------------
extern "C" void kernel_launch(void* const* d_in, const int* in_sizes, int n_in,
                              void* d_out, int out_size) {
    const float* x    = (const float*)d_in[0];
    const float* mask = (const float*)d_in[1];
    const float* W1   = (const float*)d_in[2];
    const float* b1   = (const float*)d_in[3];
    const float* g1   = (const float*)d_in[4];
    const float* be1  = (const float*)d_in[5];
    const float* W2   = (const float*)d_in[6];
    const float* b2   = (const float*)d_in[7];
    const float* g2   = (const float*)d_in[8];
    const float* be2  = (const float*)d_in[9];
    const float* Wm1  = (const float*)d_in[10];
    const float* bm1  = (const float*)d_in[11];
    const float* gm1  = (const float*)d_in[12];
    const float* bem1 = (const float*)d_in[13];
    const float* Wm2  = (const float*)d_in[14];
    const float* bm2  = (const float*)d_in[15];
    const float* gm2  = (const float*)d_in[16];
    const float* bem2 = (const float*)d_in[17];
    const float* Wm3  = (const float*)d_in[18];
    const float* bm3  = (const float*)d_in[19];
    float* out = (float*)d_out;

    static float* pHb = nullptr;
    if (!pHb) cudaGetSymbolAddress((void**)&pHb, g_Hb);

    // norms + adjacency blocks
    k_invn<<<NROWS/8, 256>>>(x);
    k_simA<<<B*NSUB, 256>>>(x, mask);

    // ---- GCN layer 1 (BN stats fused into bmm epilogue) ----
    k_xw<<<dim3(2, NROWS/128), 256>>>(x, W1, b1, 0);
    k_zero<<<1, 256>>>();
    k_bmm<<<dim3(2, B*NSUB), 256>>>();
    k_bnfin<<<1, 256>>>(g1, be1);

    // ---- GCN layer 2 (BN1+relu applied on load inside k_xw) ----
    k_xw<<<dim3(2, NROWS/128), 256>>>(pHb, W2, b2, 1);
    k_zero<<<1, 256>>>();
    k_bmm<<<dim3(2, B*NSUB), 256>>>();
    k_bnfin<<<1, 256>>>(g2, be2);

    // ---- readout + head (BN2+relu applied on load inside k_mlp1) ----
    k_mlp1<<<KCHUNKS, 256>>>(Wm1);
    k_red<<<32, 256>>>(bm1);
    k_head<<<1, 256>>>(gm1, bem1, Wm2, bm2, gm2, bem2, Wm3, bm3, out);
}

// round 4
// speedup vs baseline: 1.3983x; 1.3983x over previous
#include <cuda_runtime.h>
#include <cuda_bf16.h>
#include <math.h>
#include <stdint.h>

#define B     64
#define NSUB  4
#define PP    128
#define TP    512
#define DD    256
#define HH    256
#define FEAT  131072
#define M1    128
#define NROWS (B*TP)            // 32768
#define KCHUNKS 128             // FEAT / 1024

#define STRA  20                // A-layout: 16 packed-k words + 4 pad
#define STRB  136               // B-layout: 128 cols + 8 pad

// ---------------- scratch (device globals; no allocation) ----------------
__device__ float g_invn[B*TP];
__device__ float g_dinv[B*TP];
__device__ float g_A[(size_t)B*NSUB*PP*PP];        // 16.8 MB raw A blocks (diag=1)
__device__ float g_XW[(size_t)B*TP*HH];            // 33.5 MB
__device__ float g_Hb[(size_t)B*TP*HH];            // 33.5 MB (pre-BN h)
__device__ float g_sum[HH], g_sumsq[HH], g_scale[HH], g_shift[HH];
__device__ float g_Z1part[(size_t)KCHUNKS*B*M1];   // 4 MB split-K partials
__device__ float g_z1[B*M1];

// ---------------- bf16 split-2 helpers ----------------
// pack (a,b) into hi bf16x2 and lo bf16x2 (lo = residual)
__device__ __forceinline__ void split2(float a, float b, uint32_t& h, uint32_t& l) {
    __nv_bfloat162 hb = __floats2bfloat162_rn(a, b);
    float2 hf = __bfloat1622float2(hb);
    __nv_bfloat162 lb = __floats2bfloat162_rn(a - hf.x, b - hf.y);
    h = *(uint32_t*)&hb;
    l = *(uint32_t*)&lb;
}
__device__ __forceinline__ void mma16(float* c, const uint32_t* a, const uint32_t* b) {
    asm volatile("mma.sync.aligned.m16n8k16.row.col.f32.bf16.bf16.f32 "
                 "{%0,%1,%2,%3}, {%4,%5,%6,%7}, {%8,%9}, {%0,%1,%2,%3};\n"
                 : "+f"(c[0]), "+f"(c[1]), "+f"(c[2]), "+f"(c[3])
                 : "r"(a[0]), "r"(a[1]), "r"(a[2]), "r"(a[3]),
                   "r"(b[0]), "r"(b[1]));
}

// ---------------- 1/||x_row|| (exact fp32) + zero BN accumulators ----------------
__global__ void k_invn(const float* __restrict__ x) {
    if (blockIdx.x == 0) { g_sum[threadIdx.x] = 0.f; g_sumsq[threadIdx.x] = 0.f; }
    int row  = blockIdx.x * 8 + (threadIdx.x >> 5);
    int lane = threadIdx.x & 31;
    const float* xr = x + (size_t)row * DD;
    float s = 0.f;
#pragma unroll
    for (int i = 0; i < 8; i++) { float v = xr[lane + 32*i]; s += v*v; }
#pragma unroll
    for (int o = 16; o; o >>= 1) s += __shfl_xor_sync(0xffffffffu, s, o);
    if (lane == 0) g_invn[row] = 1.0f / fmaxf(sqrtf(s), 1e-12f);
}

// ---------------- per-(b,n): A = (cos+1)/2 * mask, diag=1; dinv ----------------
__global__ void __launch_bounds__(256) k_simA(const float* __restrict__ x,
                                              const float* __restrict__ mask) {
    __shared__ uint32_t sH[128*STRA];
    __shared__ uint32_t sL[128*STRA];
    __shared__ float sInv[128];
    __shared__ float sdeg[128];
    int bn = blockIdx.x;
    int b = bn >> 2, n = bn & 3;
    const float* Xb = x + ((size_t)b*TP + n*PP) * DD;
    int tid = threadIdx.x, w = tid >> 5, lane = tid & 31, g = lane >> 2, t = lane & 3;
    int wm = w & 3, wn = w >> 2;
    if (tid < 128) { sInv[tid] = g_invn[b*TP + n*PP + tid]; sdeg[tid] = 0.f; }

    float acc[2][8][4];
#pragma unroll
    for (int mi=0;mi<2;mi++)
#pragma unroll
        for (int ni=0;ni<8;ni++)
#pragma unroll
            for (int q=0;q<4;q++) acc[mi][ni][q] = 0.f;

    for (int k0 = 0; k0 < DD; k0 += 32) {
        __syncthreads();
#pragma unroll
        for (int it = 0; it < 4; it++) {
            int idx = tid + it*256;
            int r = idx >> 3, q = (idx & 7) * 4;
            float4 v = *(const float4*)(Xb + (size_t)r*DD + k0 + q);
            int o = r*STRA + (q >> 1);
            split2(v.x, v.y, sH[o],   sL[o]);
            split2(v.z, v.w, sH[o+1], sL[o+1]);
        }
        __syncthreads();
#pragma unroll
        for (int kb = 0; kb < 16; kb += 8) {
            uint32_t ah[2][4], al[2][4];
#pragma unroll
            for (int mi=0;mi<2;mi++) {
                int rb = wm*32 + mi*16;
                ah[mi][0] = sH[(rb+g  )*STRA + kb+t  ]; al[mi][0] = sL[(rb+g  )*STRA + kb+t  ];
                ah[mi][1] = sH[(rb+g+8)*STRA + kb+t  ]; al[mi][1] = sL[(rb+g+8)*STRA + kb+t  ];
                ah[mi][2] = sH[(rb+g  )*STRA + kb+t+4]; al[mi][2] = sL[(rb+g  )*STRA + kb+t+4];
                ah[mi][3] = sH[(rb+g+8)*STRA + kb+t+4]; al[mi][3] = sL[(rb+g+8)*STRA + kb+t+4];
            }
#pragma unroll
            for (int ni=0;ni<8;ni++) {
                int cb = wn*64 + ni*8 + g;
                uint32_t bh[2], bl[2];
                bh[0] = sH[cb*STRA + kb+t];   bl[0] = sL[cb*STRA + kb+t];
                bh[1] = sH[cb*STRA + kb+t+4]; bl[1] = sL[cb*STRA + kb+t+4];
#pragma unroll
                for (int mi=0;mi<2;mi++) {
                    mma16(acc[mi][ni], ah[mi], bh);
                    mma16(acc[mi][ni], ah[mi], bl);
                    mma16(acc[mi][ni], al[mi], bh);
                }
            }
        }
    }
    __syncthreads();

    float* Ab = g_A + (size_t)bn * (PP*PP);
#pragma unroll
    for (int ni=0;ni<8;ni++) {
        int c0 = wn*64 + ni*8 + 2*t, c1 = c0 + 1;
        float ic0 = sInv[c0], ic1 = sInv[c1];
#pragma unroll
        for (int mi=0;mi<2;mi++) {
            int r0 = wm*32 + mi*16 + g, r1 = r0 + 8;
            float i0 = sInv[r0], i1 = sInv[r1];
            float v00 = (r0==c0) ? 1.f : (acc[mi][ni][0]*i0*ic0 + 1.f)*0.5f*mask[r0*PP+c0];
            float v01 = (r0==c1) ? 1.f : (acc[mi][ni][1]*i0*ic1 + 1.f)*0.5f*mask[r0*PP+c1];
            float v10 = (r1==c0) ? 1.f : (acc[mi][ni][2]*i1*ic0 + 1.f)*0.5f*mask[r1*PP+c0];
            float v11 = (r1==c1) ? 1.f : (acc[mi][ni][3]*i1*ic1 + 1.f)*0.5f*mask[r1*PP+c1];
            *(float2*)&Ab[r0*PP + c0] = make_float2(v00, v01);
            *(float2*)&Ab[r1*PP + c0] = make_float2(v10, v11);
            atomicAdd(&sdeg[r0], v00 + v01);
            atomicAdd(&sdeg[r1], v10 + v11);
        }
    }
    __syncthreads();
    if (tid < 128) {
        float deg = sdeg[tid];
        g_dinv[b*TP + n*PP + tid] = (deg > 0.f) ? rsqrtf(fmaxf(deg, 1e-12f)) : 0.f;
    }
}

// ---------------- [32768,256] @ [256,256] + bias -> g_XW (bf16x3) ----------------
// bn=1: input A holds raw pre-BN h; apply relu(v*g_scale[c]+g_shift[c]) on load.
__global__ void __launch_bounds__(256) k_xw(const float* __restrict__ A,
                                            const float* __restrict__ W,
                                            const float* __restrict__ bias,
                                            int bn) {
    __shared__ uint32_t sAH[128*STRA];
    __shared__ uint32_t sAL[128*STRA];
    __shared__ uint32_t sBH[16*STRB];
    __shared__ uint32_t sBL[16*STRB];
    __shared__ float sSc[256], sSh[256];
    int tid = threadIdx.x, w = tid >> 5, lane = tid & 31, g = lane >> 2, t = lane & 3;
    int wm = w & 3, wn = w >> 2;
    int m0 = blockIdx.y * 128, n0 = blockIdx.x * 128;
    if (bn) { sSc[tid] = g_scale[tid]; sSh[tid] = g_shift[tid]; }
    float acc[2][8][4];
#pragma unroll
    for (int mi=0;mi<2;mi++)
#pragma unroll
        for (int ni=0;ni<8;ni++)
#pragma unroll
            for (int q=0;q<4;q++) acc[mi][ni][q] = 0.f;

    for (int k0 = 0; k0 < 256; k0 += 32) {
        __syncthreads();
#pragma unroll
        for (int it = 0; it < 4; it++) {
            int idx = tid + it*256;
            int r = idx >> 3, q = (idx & 7) * 4;
            float4 v = *(const float4*)(A + (size_t)(m0+r)*256 + k0 + q);
            if (bn) {
                int c = k0 + q;
                v.x = fmaxf(fmaf(v.x, sSc[c],   sSh[c]),   0.f);
                v.y = fmaxf(fmaf(v.y, sSc[c+1], sSh[c+1]), 0.f);
                v.z = fmaxf(fmaf(v.z, sSc[c+2], sSh[c+2]), 0.f);
                v.w = fmaxf(fmaf(v.w, sSc[c+3], sSh[c+3]), 0.f);
            }
            int o = r*STRA + (q >> 1);
            split2(v.x, v.y, sAH[o],   sAL[o]);
            split2(v.z, v.w, sAH[o+1], sAL[o+1]);
        }
#pragma unroll
        for (int it = 0; it < 2; it++) {
            int idx = tid + it*256;
            int r = idx >> 5, q = (idx & 31) * 4;   // r: kk2 0..15, q: col
            const float* w0 = W + (size_t)(k0 + 2*r    )*256 + n0 + q;
            const float* w1 = W + (size_t)(k0 + 2*r + 1)*256 + n0 + q;
            float4 v0 = *(const float4*)w0;
            float4 v1 = *(const float4*)w1;
            int o = r*STRB + q;
            split2(v0.x, v1.x, sBH[o],   sBL[o]);
            split2(v0.y, v1.y, sBH[o+1], sBL[o+1]);
            split2(v0.z, v1.z, sBH[o+2], sBL[o+2]);
            split2(v0.w, v1.w, sBH[o+3], sBL[o+3]);
        }
        __syncthreads();
#pragma unroll
        for (int kb = 0; kb < 16; kb += 8) {
            uint32_t ah[2][4], al[2][4];
#pragma unroll
            for (int mi=0;mi<2;mi++) {
                int rb = wm*32 + mi*16;
                ah[mi][0] = sAH[(rb+g  )*STRA + kb+t  ]; al[mi][0] = sAL[(rb+g  )*STRA + kb+t  ];
                ah[mi][1] = sAH[(rb+g+8)*STRA + kb+t  ]; al[mi][1] = sAL[(rb+g+8)*STRA + kb+t  ];
                ah[mi][2] = sAH[(rb+g  )*STRA + kb+t+4]; al[mi][2] = sAL[(rb+g  )*STRA + kb+t+4];
                ah[mi][3] = sAH[(rb+g+8)*STRA + kb+t+4]; al[mi][3] = sAL[(rb+g+8)*STRA + kb+t+4];
            }
#pragma unroll
            for (int ni=0;ni<8;ni++) {
                int cb = wn*64 + ni*8 + g;
                uint32_t bh[2], bl[2];
                bh[0] = sBH[(kb+t  )*STRB + cb]; bl[0] = sBL[(kb+t  )*STRB + cb];
                bh[1] = sBH[(kb+t+4)*STRB + cb]; bl[1] = sBL[(kb+t+4)*STRB + cb];
#pragma unroll
                for (int mi=0;mi<2;mi++) {
                    mma16(acc[mi][ni], ah[mi], bh);
                    mma16(acc[mi][ni], ah[mi], bl);
                    mma16(acc[mi][ni], al[mi], bh);
                }
            }
        }
    }
#pragma unroll
    for (int mi=0;mi<2;mi++) {
        int r0 = m0 + wm*32 + mi*16 + g, r1 = r0 + 8;
#pragma unroll
        for (int ni=0;ni<8;ni++) {
            int c0 = n0 + wn*64 + ni*8 + 2*t;
            float b0 = bias[c0], b1 = bias[c0+1];
            *(float2*)&g_XW[(size_t)r0*256 + c0] = make_float2(acc[mi][ni][0] + b0, acc[mi][ni][1] + b1);
            *(float2*)&g_XW[(size_t)r1*256 + c0] = make_float2(acc[mi][ni][2] + b0, acc[mi][ni][3] + b1);
        }
    }
}

// ---------------- H = dinv_i * A(b,n) @ (dinv_j * XW) (bf16x3) + fused BN stats ----------------
__global__ void __launch_bounds__(256) k_bmm() {
    __shared__ uint32_t sAH[128*STRA];
    __shared__ uint32_t sAL[128*STRA];
    __shared__ uint32_t sBH[16*STRB];
    __shared__ uint32_t sBL[16*STRB];
    __shared__ float sDv[128];
    __shared__ float sSum[128], sSq[128];
    int bn = blockIdx.y;
    int b = bn >> 2, n = bn & 3;
    int h0 = blockIdx.x * 128;
    const float* Ab    = g_A + (size_t)bn * (PP*PP);
    const float* Xrows = g_XW + ((size_t)(b*TP + n*PP)) * HH;
    int tid = threadIdx.x, w = tid >> 5, lane = tid & 31, g = lane >> 2, t = lane & 3;
    int wm = w & 3, wn = w >> 2;
    if (tid < 128) { sDv[tid] = g_dinv[b*TP + n*PP + tid]; sSum[tid] = 0.f; sSq[tid] = 0.f; }

    float acc[2][8][4];
#pragma unroll
    for (int mi=0;mi<2;mi++)
#pragma unroll
        for (int ni=0;ni<8;ni++)
#pragma unroll
            for (int q=0;q<4;q++) acc[mi][ni][q] = 0.f;

    for (int k0 = 0; k0 < PP; k0 += 32) {
        __syncthreads();
#pragma unroll
        for (int it = 0; it < 4; it++) {
            int idx = tid + it*256;
            int r = idx >> 3, q = (idx & 7) * 4;
            float4 v = *(const float4*)(Ab + (size_t)r*PP + k0 + q);
            int o = r*STRA + (q >> 1);
            split2(v.x, v.y, sAH[o],   sAL[o]);
            split2(v.z, v.w, sAH[o+1], sAL[o+1]);
        }
#pragma unroll
        for (int it = 0; it < 2; it++) {
            int idx = tid + it*256;
            int r = idx >> 5, q = (idx & 31) * 4;
            float d0 = sDv[k0 + 2*r], d1 = sDv[k0 + 2*r + 1];
            float4 v0 = *(const float4*)(Xrows + (size_t)(k0 + 2*r    )*HH + h0 + q);
            float4 v1 = *(const float4*)(Xrows + (size_t)(k0 + 2*r + 1)*HH + h0 + q);
            int o = r*STRB + q;
            split2(v0.x*d0, v1.x*d1, sBH[o],   sBL[o]);
            split2(v0.y*d0, v1.y*d1, sBH[o+1], sBL[o+1]);
            split2(v0.z*d0, v1.z*d1, sBH[o+2], sBL[o+2]);
            split2(v0.w*d0, v1.w*d1, sBH[o+3], sBL[o+3]);
        }
        __syncthreads();
#pragma unroll
        for (int kb = 0; kb < 16; kb += 8) {
            uint32_t ah[2][4], al[2][4];
#pragma unroll
            for (int mi=0;mi<2;mi++) {
                int rb = wm*32 + mi*16;
                ah[mi][0] = sAH[(rb+g  )*STRA + kb+t  ]; al[mi][0] = sAL[(rb+g  )*STRA + kb+t  ];
                ah[mi][1] = sAH[(rb+g+8)*STRA + kb+t  ]; al[mi][1] = sAL[(rb+g+8)*STRA + kb+t  ];
                ah[mi][2] = sAH[(rb+g  )*STRA + kb+t+4]; al[mi][2] = sAL[(rb+g  )*STRA + kb+t+4];
                ah[mi][3] = sAH[(rb+g+8)*STRA + kb+t+4]; al[mi][3] = sAL[(rb+g+8)*STRA + kb+t+4];
            }
#pragma unroll
            for (int ni=0;ni<8;ni++) {
                int cb = wn*64 + ni*8 + g;
                uint32_t bh[2], bl[2];
                bh[0] = sBH[(kb+t  )*STRB + cb]; bl[0] = sBL[(kb+t  )*STRB + cb];
                bh[1] = sBH[(kb+t+4)*STRB + cb]; bl[1] = sBL[(kb+t+4)*STRB + cb];
#pragma unroll
                for (int mi=0;mi<2;mi++) {
                    mma16(acc[mi][ni], ah[mi], bh);
                    mma16(acc[mi][ni], ah[mi], bl);
                    mma16(acc[mi][ni], al[mi], bh);
                }
            }
        }
    }
    float* base = g_Hb + ((size_t)(b*TP + n*PP)) * HH;
#pragma unroll
    for (int ni=0;ni<8;ni++) {
        int cl = wn*64 + ni*8 + 2*t;
        float cs0 = 0.f, cs1 = 0.f, cq0 = 0.f, cq1 = 0.f;
#pragma unroll
        for (int mi=0;mi<2;mi++) {
            int r0 = wm*32 + mi*16 + g, r1 = r0 + 8;
            float d0 = sDv[r0], d1 = sDv[r1];
            float v00 = acc[mi][ni][0]*d0, v01 = acc[mi][ni][1]*d0;
            float v10 = acc[mi][ni][2]*d1, v11 = acc[mi][ni][3]*d1;
            *(float2*)&base[(size_t)r0*HH + h0 + cl] = make_float2(v00, v01);
            *(float2*)&base[(size_t)r1*HH + h0 + cl] = make_float2(v10, v11);
            cs0 += v00 + v10; cs1 += v01 + v11;
            cq0 += v00*v00 + v10*v10; cq1 += v01*v01 + v11*v11;
        }
        atomicAdd(&sSum[cl],   cs0);
        atomicAdd(&sSum[cl+1], cs1);
        atomicAdd(&sSq[cl],    cq0);
        atomicAdd(&sSq[cl+1],  cq1);
    }
    __syncthreads();
    if (tid < 128) {
        atomicAdd(&g_sum[h0 + tid],   sSum[tid]);
        atomicAdd(&g_sumsq[h0 + tid], sSq[tid]);
    }
}

// ---------------- BN finalize (also re-zeros accumulators for next layer) ----------------
__global__ void k_bnfin(const float* __restrict__ g, const float* __restrict__ be) {
    int c = threadIdx.x;
    const float invn = 1.0f / (float)NROWS;
    float m = g_sum[c] * invn;
    float v = g_sumsq[c] * invn - m*m;
    float sc = g[c] * rsqrtf(v + 1e-5f);
    g_scale[c] = sc;
    g_shift[c] = be[c] - m*sc;
    g_sum[c] = 0.f;
    g_sumsq[c] = 0.f;
}

// ---------------- split-K readout GEMM (bf16x3), BN2+relu fused on load ----------------
__global__ void __launch_bounds__(256) k_mlp1(const float* __restrict__ Wm1) {
    __shared__ uint32_t sGH[64*STRA];
    __shared__ uint32_t sGL[64*STRA];
    __shared__ uint32_t sWH[16*STRB];
    __shared__ uint32_t sWL[16*STRB];
    __shared__ float sSc[256], sSh[256];
    int kc = blockIdx.x;
    int kbase = kc * 1024;
    int tid = threadIdx.x, w = tid >> 5, lane = tid & 31, g = lane >> 2, t = lane & 3;
    int wm = w & 3, wn = w >> 2;
    sSc[tid] = g_scale[tid]; sSh[tid] = g_shift[tid];
    float acc[8][4];
#pragma unroll
    for (int ni=0;ni<8;ni++)
#pragma unroll
        for (int q=0;q<4;q++) acc[ni][q] = 0.f;

    for (int k0 = 0; k0 < 1024; k0 += 32) {
        __syncthreads();
#pragma unroll
        for (int it = 0; it < 2; it++) {
            int idx = tid + it*256;
            int r = idx >> 3, q = (idx & 7) * 4;
            int c = (k0 + q) & 255;
            float4 v = *(const float4*)(g_Hb + (size_t)r*FEAT + kbase + k0 + q);
            v.x = fmaxf(fmaf(v.x, sSc[c],   sSh[c]),   0.f);
            v.y = fmaxf(fmaf(v.y, sSc[c+1], sSh[c+1]), 0.f);
            v.z = fmaxf(fmaf(v.z, sSc[c+2], sSh[c+2]), 0.f);
            v.w = fmaxf(fmaf(v.w, sSc[c+3], sSh[c+3]), 0.f);
            int o = r*STRA + (q >> 1);
            split2(v.x, v.y, sGH[o],   sGL[o]);
            split2(v.z, v.w, sGH[o+1], sGL[o+1]);
        }
#pragma unroll
        for (int it = 0; it < 2; it++) {
            int idx = tid + it*256;
            int r = idx >> 5, q = (idx & 31) * 4;
            float4 v0 = *(const float4*)(Wm1 + (size_t)(kbase + k0 + 2*r    )*128 + q);
            float4 v1 = *(const float4*)(Wm1 + (size_t)(kbase + k0 + 2*r + 1)*128 + q);
            int o = r*STRB + q;
            split2(v0.x, v1.x, sWH[o],   sWL[o]);
            split2(v0.y, v1.y, sWH[o+1], sWL[o+1]);
            split2(v0.z, v1.z, sWH[o+2], sWL[o+2]);
            split2(v0.w, v1.w, sWH[o+3], sWL[o+3]);
        }
        __syncthreads();
#pragma unroll
        for (int kb = 0; kb < 16; kb += 8) {
            uint32_t ah[4], al[4];
            int rb = wm*16;
            ah[0] = sGH[(rb+g  )*STRA + kb+t  ]; al[0] = sGL[(rb+g  )*STRA + kb+t  ];
            ah[1] = sGH[(rb+g+8)*STRA + kb+t  ]; al[1] = sGL[(rb+g+8)*STRA + kb+t  ];
            ah[2] = sGH[(rb+g  )*STRA + kb+t+4]; al[2] = sGL[(rb+g  )*STRA + kb+t+4];
            ah[3] = sGH[(rb+g+8)*STRA + kb+t+4]; al[3] = sGL[(rb+g+8)*STRA + kb+t+4];
#pragma unroll
            for (int ni=0;ni<8;ni++) {
                int cb = wn*64 + ni*8 + g;
                uint32_t bh[2], bl[2];
                bh[0] = sWH[(kb+t  )*STRB + cb]; bl[0] = sWL[(kb+t  )*STRB + cb];
                bh[1] = sWH[(kb+t+4)*STRB + cb]; bl[1] = sWL[(kb+t+4)*STRB + cb];
                mma16(acc[ni], ah, bh);
                mma16(acc[ni], ah, bl);
                mma16(acc[ni], al, bh);
            }
        }
    }
    float* out = g_Z1part + (size_t)kc * (B*M1);
    int r0 = wm*16 + g, r1 = r0 + 8;
#pragma unroll
    for (int ni=0;ni<8;ni++) {
        int c0 = wn*64 + ni*8 + 2*t;
        *(float2*)&out[r0*M1 + c0] = make_float2(acc[ni][0], acc[ni][1]);
        *(float2*)&out[r1*M1 + c0] = make_float2(acc[ni][2], acc[ni][3]);
    }
}

__global__ void k_red(const float* __restrict__ bm1) {
    int o = blockIdx.x*256 + threadIdx.x;   // 0..8191
    float s = bm1[o & 127];
    for (int kc = 0; kc < KCHUNKS; kc++) s += g_Z1part[(size_t)kc*(B*M1) + o];
    g_z1[o] = s;
}

// ---------------- head: bn1d+relu, z@Wm2, bn1d+relu, z@Wm3 (exact fp32) ----------------
__global__ void __launch_bounds__(256) k_head(const float* __restrict__ gm1, const float* __restrict__ bem1,
                                              const float* __restrict__ Wm2, const float* __restrict__ bm2,
                                              const float* __restrict__ gm2, const float* __restrict__ bem2,
                                              const float* __restrict__ Wm3, const float* __restrict__ bm3,
                                              float* __restrict__ out) {
    __shared__ float sz1[64][128];
    __shared__ float sz2[64][64];
    int tid = threadIdx.x;

    if (tid < 128) {
        float s = 0.f, s2 = 0.f;
        for (int b = 0; b < 64; b++) { float v = g_z1[b*128 + tid]; s += v; s2 += v*v; }
        float m = s * (1.f/64.f), var = s2 * (1.f/64.f) - m*m;
        float sc = gm1[tid] * rsqrtf(var + 1e-5f);
        float sh = bem1[tid] - m*sc;
        for (int b = 0; b < 64; b++)
            sz1[b][tid] = fmaxf(fmaf(g_z1[b*128 + tid], sc, sh), 0.f);
    }
    __syncthreads();

    for (int o = tid; o < 4096; o += 256) {
        int b = o >> 6, j = o & 63;
        float s = bm2[j];
#pragma unroll 8
        for (int m = 0; m < 128; m++) s = fmaf(sz1[b][m], Wm2[m*64 + j], s);
        sz2[b][j] = s;
    }
    __syncthreads();

    if (tid < 64) {
        float s = 0.f, s2 = 0.f;
        for (int b = 0; b < 64; b++) { float v = sz2[b][tid]; s += v; s2 += v*v; }
        float m = s * (1.f/64.f), var = s2 * (1.f/64.f) - m*m;
        float sc = gm2[tid] * rsqrtf(var + 1e-5f);
        float sh = bem2[tid] - m*sc;
        for (int b = 0; b < 64; b++)
            sz2[b][tid] = fmaxf(fmaf(sz2[b][tid], sc, sh), 0.f);
    }
    __syncthreads();

    if (tid < 128) {
        int b = tid >> 1, c = tid & 1;
        float s = bm3[c];
#pragma unroll
        for (int j = 0; j < 64; j++) s = fmaf(sz2[b][j], Wm3[j*2 + c], s);
        out[b*2 + c] = s;
    }
}

// ---------------- launch ----------------
extern "C" void kernel_launch(void* const* d_in, const int* in_sizes, int n_in,
                              void* d_out, int out_size) {
    const float* x    = (const float*)d_in[0];
    const float* mask = (const float*)d_in[1];
    const float* W1   = (const float*)d_in[2];
    const float* b1   = (const float*)d_in[3];
    const float* g1   = (const float*)d_in[4];
    const float* be1  = (const float*)d_in[5];
    const float* W2   = (const float*)d_in[6];
    const float* b2   = (const float*)d_in[7];
    const float* g2   = (const float*)d_in[8];
    const float* be2  = (const float*)d_in[9];
    const float* Wm1  = (const float*)d_in[10];
    const float* bm1  = (const float*)d_in[11];
    const float* gm1  = (const float*)d_in[12];
    const float* bem1 = (const float*)d_in[13];
    const float* Wm2  = (const float*)d_in[14];
    const float* bm2  = (const float*)d_in[15];
    const float* gm2  = (const float*)d_in[16];
    const float* bem2 = (const float*)d_in[17];
    const float* Wm3  = (const float*)d_in[18];
    const float* bm3  = (const float*)d_in[19];
    float* out = (float*)d_out;

    static float* pHb = nullptr;
    if (!pHb) cudaGetSymbolAddress((void**)&pHb, g_Hb);

    // norms + adjacency blocks (k_invn also zeros BN accumulators)
    k_invn<<<NROWS/8, 256>>>(x);
    k_simA<<<B*NSUB, 256>>>(x, mask);

    // ---- GCN layer 1 (BN stats fused into bmm epilogue) ----
    k_xw<<<dim3(2, NROWS/128), 256>>>(x, W1, b1, 0);
    k_bmm<<<dim3(2, B*NSUB), 256>>>();
    k_bnfin<<<1, 256>>>(g1, be1);

    // ---- GCN layer 2 (BN1+relu applied on load inside k_xw) ----
    k_xw<<<dim3(2, NROWS/128), 256>>>(pHb, W2, b2, 1);
    k_bmm<<<dim3(2, B*NSUB), 256>>>();
    k_bnfin<<<1, 256>>>(g2, be2);

    // ---- readout + head (BN2+relu applied on load inside k_mlp1) ----
    k_mlp1<<<KCHUNKS, 256>>>(Wm1);
    k_red<<<32, 256>>>(bm1);
    k_head<<<1, 256>>>(gm1, bem1, Wm2, bm2, gm2, bem2, Wm3, bm3, out);
}

// round 5
// speedup vs baseline: 1.6182x; 1.1573x over previous
#include <cuda_runtime.h>
#include <cuda_bf16.h>
#include <math.h>
#include <stdint.h>

#define B     64
#define NSUB  4
#define PP    128
#define TP    512
#define DD    256
#define HH    256
#define FEAT  131072
#define M1    128
#define NROWS (B*TP)            // 32768
#define KCHUNKS 256             // split-K chunks for mlp1 (512 K each)

#define STRA  20                // A-tile stride (16 kpair words + 4 pad)
#define STRB  136               // B-tile stride (128 cols + 8 pad)

// ---------------- scratch (device globals; no allocation) ----------------
__device__ float    g_invn[B*TP];
__device__ float    g_dinv[B*TP];
__device__ uint32_t g_Xh[(size_t)NROWS*128];       // x split hi (packed bf16x2 along d)
__device__ uint32_t g_Xl[(size_t)NROWS*128];
__device__ uint32_t g_Ah[(size_t)256*PP*64];       // adjacency hi (packed along k)
__device__ uint32_t g_Al[(size_t)256*PP*64];
__device__ uint32_t g_W1h[128*256], g_W1l[128*256]; // W kpairN packed
__device__ uint32_t g_W2h[128*256], g_W2l[128*256];
__device__ uint32_t g_XWh[(size_t)(NROWS/2)*256];  // XW*dinv+bias, kpairN packed
__device__ uint32_t g_XWl[(size_t)(NROWS/2)*256];
__device__ float    g_Hb[(size_t)NROWS*HH];        // pre-BN h (fp32)
__device__ uint32_t g_Hbh[(size_t)NROWS*128];      // post-BN h split (rowK packed)
__device__ uint32_t g_Hbl[(size_t)NROWS*128];
__device__ float    g_sum[HH], g_sumsq[HH], g_scale[HH], g_shift[HH];
__device__ float    g_Z1part[(size_t)KCHUNKS*B*M1];
__device__ float    g_z1[B*M1];

// ---------------- helpers ----------------
__device__ __forceinline__ void split2(float a, float b, uint32_t& h, uint32_t& l) {
    __nv_bfloat162 hb = __floats2bfloat162_rn(a, b);
    float2 hf = __bfloat1622float2(hb);
    __nv_bfloat162 lb = __floats2bfloat162_rn(a - hf.x, b - hf.y);
    h = *(uint32_t*)&hb;
    l = *(uint32_t*)&lb;
}
__device__ __forceinline__ void mma16(float* c, const uint32_t* a, const uint32_t* b) {
    asm volatile("mma.sync.aligned.m16n8k16.row.col.f32.bf16.bf16.f32 "
                 "{%0,%1,%2,%3}, {%4,%5,%6,%7}, {%8,%9}, {%0,%1,%2,%3};\n"
                 : "+f"(c[0]), "+f"(c[1]), "+f"(c[2]), "+f"(c[3])
                 : "r"(a[0]), "r"(a[1]), "r"(a[2]), "r"(a[3]),
                   "r"(b[0]), "r"(b[1]));
}
__device__ __forceinline__ void cpa(uint32_t* dst, const void* src) {
    uint32_t d = (uint32_t)__cvta_generic_to_shared(dst);
    asm volatile("cp.async.cg.shared.global [%0], [%1], 16;" :: "r"(d), "l"(src));
}
#define CP_COMMIT() asm volatile("cp.async.commit_group;")
#define CP_WAIT0()  asm volatile("cp.async.wait_group 0;")

// ---------------- 1/||x_row|| + zero BN accumulators ----------------
__global__ void k_invn(const float* __restrict__ x) {
    if (blockIdx.x == 0) { g_sum[threadIdx.x] = 0.f; g_sumsq[threadIdx.x] = 0.f; }
    int row  = blockIdx.x * 8 + (threadIdx.x >> 5);
    int lane = threadIdx.x & 31;
    const float* xr = x + (size_t)row * DD;
    float s = 0.f;
#pragma unroll
    for (int i = 0; i < 8; i++) { float v = xr[lane + 32*i]; s += v*v; }
#pragma unroll
    for (int o = 16; o; o >>= 1) s += __shfl_xor_sync(0xffffffffu, s, o);
    if (lane == 0) g_invn[row] = 1.0f / fmaxf(sqrtf(s), 1e-12f);
}

// ---------------- split x -> g_Xh/g_Xl (rowK packed) ----------------
__global__ void k_splitX(const float* __restrict__ x) {
    size_t i4 = (size_t)blockIdx.x * 256 + threadIdx.x;   // one float4 each
    float4 v = ((const float4*)x)[i4];
    uint32_t h0, l0, h1, l1;
    split2(v.x, v.y, h0, l0);
    split2(v.z, v.w, h1, l1);
    ((uint2*)g_Xh)[i4] = make_uint2(h0, h1);
    ((uint2*)g_Xl)[i4] = make_uint2(l0, l1);
}

// ---------------- BN+relu+split: g_Hb -> g_Hbh/g_Hbl ----------------
__global__ void k_bnsplit() {
    __shared__ float sSc[256], sSh[256];
    sSc[threadIdx.x] = g_scale[threadIdx.x];
    sSh[threadIdx.x] = g_shift[threadIdx.x];
    __syncthreads();
    size_t i4 = (size_t)blockIdx.x * 256 + threadIdx.x;
    float4 v = ((const float4*)g_Hb)[i4];
    int c = (int)((i4 * 4) & 255);
    v.x = fmaxf(fmaf(v.x, sSc[c],   sSh[c]),   0.f);
    v.y = fmaxf(fmaf(v.y, sSc[c+1], sSh[c+1]), 0.f);
    v.z = fmaxf(fmaf(v.z, sSc[c+2], sSh[c+2]), 0.f);
    v.w = fmaxf(fmaf(v.w, sSc[c+3], sSh[c+3]), 0.f);
    uint32_t h0, l0, h1, l1;
    split2(v.x, v.y, h0, l0);
    split2(v.z, v.w, h1, l1);
    ((uint2*)g_Hbh)[i4] = make_uint2(h0, h1);
    ((uint2*)g_Hbl)[i4] = make_uint2(l0, l1);
}

// ---------------- split W [256][256] -> kpairN packed [128][256] ----------------
__global__ void k_splitW(const float* __restrict__ W,
                         uint32_t* __restrict__ Wh, uint32_t* __restrict__ Wl) {
    int idx = blockIdx.x * 256 + threadIdx.x;   // 0..8191
    int kp = idx >> 6, c = (idx & 63) * 4;
    float4 a = *(const float4*)&W[(2*kp)*256 + c];
    float4 b = *(const float4*)&W[(2*kp+1)*256 + c];
    uint4 H, L;
    split2(a.x, b.x, H.x, L.x);
    split2(a.y, b.y, H.y, L.y);
    split2(a.z, b.z, H.z, L.z);
    split2(a.w, b.w, H.w, L.w);
    *(uint4*)&Wh[kp*256 + c] = H;
    *(uint4*)&Wl[kp*256 + c] = L;
}

// ---------------- per-(b,n): A = (cos+1)/2 * mask, diag=1 -> g_Ah/l, dinv ----------------
__global__ void __launch_bounds__(256) k_simA(const float* __restrict__ mask) {
    __shared__ uint32_t S[10240];   // 2 stages x (hi 2560 + lo 2560)
    __shared__ float sInv[128];
    __shared__ float sdeg[128];
    int bn = blockIdx.x;
    int b = bn >> 2, n = bn & 3;
    int rowbase = b*TP + n*PP;
    int tid = threadIdx.x, w = tid >> 5, lane = tid & 31, g = lane >> 2, t = lane & 3;
    int wm = w & 3, wn = w >> 2;
    if (tid < 128) { sInv[tid] = g_invn[rowbase + tid]; sdeg[tid] = 0.f; }

    float acc[2][8][4];
#pragma unroll
    for (int mi=0;mi<2;mi++)
#pragma unroll
        for (int ni=0;ni<8;ni++)
#pragma unroll
            for (int q=0;q<4;q++) acc[mi][ni][q] = 0.f;

    // issue chunk 0
    {
        int kc = 0;
#pragma unroll
        for (int it = 0; it < 2; it++) {
            int idx = tid + it*256;
            int r = idx >> 2, q = (idx & 3) * 4;
            cpa(&S[r*STRA + q],        g_Xh + (size_t)(rowbase + r)*128 + kc*16 + q);
            cpa(&S[2560 + r*STRA + q], g_Xl + (size_t)(rowbase + r)*128 + kc*16 + q);
        }
        CP_COMMIT();
    }
    for (int it = 0; it < 8; it++) {
        CP_WAIT0();
        __syncthreads();
        if (it + 1 < 8) {
            int st = (it+1) & 1, kc = it+1;
#pragma unroll
            for (int i2 = 0; i2 < 2; i2++) {
                int idx = tid + i2*256;
                int r = idx >> 2, q = (idx & 3) * 4;
                cpa(&S[st*5120 + r*STRA + q],        g_Xh + (size_t)(rowbase + r)*128 + kc*16 + q);
                cpa(&S[st*5120 + 2560 + r*STRA + q], g_Xl + (size_t)(rowbase + r)*128 + kc*16 + q);
            }
            CP_COMMIT();
        }
        const uint32_t* H = S + (it&1)*5120;
        const uint32_t* L = H + 2560;
#pragma unroll
        for (int kb = 0; kb < 16; kb += 8) {
            uint32_t ah[2][4], al[2][4];
#pragma unroll
            for (int mi=0;mi<2;mi++) {
                int rb = wm*32 + mi*16;
                ah[mi][0] = H[(rb+g  )*STRA + kb+t  ]; al[mi][0] = L[(rb+g  )*STRA + kb+t  ];
                ah[mi][1] = H[(rb+g+8)*STRA + kb+t  ]; al[mi][1] = L[(rb+g+8)*STRA + kb+t  ];
                ah[mi][2] = H[(rb+g  )*STRA + kb+t+4]; al[mi][2] = L[(rb+g  )*STRA + kb+t+4];
                ah[mi][3] = H[(rb+g+8)*STRA + kb+t+4]; al[mi][3] = L[(rb+g+8)*STRA + kb+t+4];
            }
#pragma unroll
            for (int ni=0;ni<8;ni++) {
                int cb = wn*64 + ni*8 + g;
                uint32_t bh[2], bl[2];
                bh[0] = H[cb*STRA + kb+t];   bl[0] = L[cb*STRA + kb+t];
                bh[1] = H[cb*STRA + kb+t+4]; bl[1] = L[cb*STRA + kb+t+4];
#pragma unroll
                for (int mi=0;mi<2;mi++) {
                    mma16(acc[mi][ni], ah[mi], bh);
                    mma16(acc[mi][ni], ah[mi], bl);
                    mma16(acc[mi][ni], al[mi], bh);
                }
            }
        }
    }
    __syncthreads();

#pragma unroll
    for (int ni=0;ni<8;ni++) {
        int c0 = wn*64 + ni*8 + 2*t, c1 = c0 + 1;
        float ic0 = sInv[c0], ic1 = sInv[c1];
#pragma unroll
        for (int mi=0;mi<2;mi++) {
            int r0 = wm*32 + mi*16 + g, r1 = r0 + 8;
            float i0 = sInv[r0], i1 = sInv[r1];
            float v00 = (r0==c0) ? 1.f : (acc[mi][ni][0]*i0*ic0 + 1.f)*0.5f*mask[r0*PP+c0];
            float v01 = (r0==c1) ? 1.f : (acc[mi][ni][1]*i0*ic1 + 1.f)*0.5f*mask[r0*PP+c1];
            float v10 = (r1==c0) ? 1.f : (acc[mi][ni][2]*i1*ic0 + 1.f)*0.5f*mask[r1*PP+c0];
            float v11 = (r1==c1) ? 1.f : (acc[mi][ni][3]*i1*ic1 + 1.f)*0.5f*mask[r1*PP+c1];
            uint32_t h, l;
            split2(v00, v01, h, l);
            g_Ah[((size_t)bn*128 + r0)*64 + (c0>>1)] = h;
            g_Al[((size_t)bn*128 + r0)*64 + (c0>>1)] = l;
            split2(v10, v11, h, l);
            g_Ah[((size_t)bn*128 + r1)*64 + (c0>>1)] = h;
            g_Al[((size_t)bn*128 + r1)*64 + (c0>>1)] = l;
            atomicAdd(&sdeg[r0], v00 + v01);
            atomicAdd(&sdeg[r1], v10 + v11);
        }
    }
    __syncthreads();
    if (tid < 128) {
        float deg = sdeg[tid];
        g_dinv[rowbase + tid] = (deg > 0.f) ? rsqrtf(fmaxf(deg, 1e-12f)) : 0.f;
    }
}

// ---------------- XW = A @ W + bias, x dinv_row -> g_XWh/l (kpairN packed) ----------------
// A-side: rowK packed (g_Xh/l or g_Hbh/l). B-side: kpairN packed W.
__global__ void __launch_bounds__(256) k_xw(const uint32_t* __restrict__ Ah,
                                            const uint32_t* __restrict__ Al,
                                            const uint32_t* __restrict__ Wh,
                                            const uint32_t* __restrict__ Wl,
                                            const float* __restrict__ bias) {
    extern __shared__ uint32_t S[];   // 18944 words
    __shared__ float sDv[128];
    int tid = threadIdx.x, w = tid >> 5, lane = tid & 31, g = lane >> 2, t = lane & 3;
    int wm = w & 3, wn = w >> 2;
    int m0 = blockIdx.y * 128, n0 = blockIdx.x * 128;
    if (tid < 128) sDv[tid] = g_dinv[m0 + tid];

    float acc[2][8][4];
#pragma unroll
    for (int mi=0;mi<2;mi++)
#pragma unroll
        for (int ni=0;ni<8;ni++)
#pragma unroll
            for (int q=0;q<4;q++) acc[mi][ni][q] = 0.f;

    // issue chunk 0
    {
        int kc = 0;
#pragma unroll
        for (int i2 = 0; i2 < 2; i2++) {
            int idx = tid + i2*256;
            int r = idx >> 2, q = (idx & 3) * 4;
            cpa(&S[r*STRA + q],        Ah + (size_t)(m0 + r)*128 + kc*16 + q);
            cpa(&S[2560 + r*STRA + q], Al + (size_t)(m0 + r)*128 + kc*16 + q);
        }
#pragma unroll
        for (int i2 = 0; i2 < 2; i2++) {
            int idx = tid + i2*256;
            int kp = idx >> 5, c = (idx & 31) * 4;
            cpa(&S[10240 + kp*STRB + c], Wh + (size_t)(kc*16 + kp)*256 + n0 + c);
            cpa(&S[12416 + kp*STRB + c], Wl + (size_t)(kc*16 + kp)*256 + n0 + c);
        }
        CP_COMMIT();
    }
    for (int it = 0; it < 8; it++) {
        CP_WAIT0();
        __syncthreads();
        if (it + 1 < 8) {
            int st = (it+1) & 1, kc = it+1;
#pragma unroll
            for (int i2 = 0; i2 < 2; i2++) {
                int idx = tid + i2*256;
                int r = idx >> 2, q = (idx & 3) * 4;
                cpa(&S[st*5120 + r*STRA + q],        Ah + (size_t)(m0 + r)*128 + kc*16 + q);
                cpa(&S[st*5120 + 2560 + r*STRA + q], Al + (size_t)(m0 + r)*128 + kc*16 + q);
            }
#pragma unroll
            for (int i2 = 0; i2 < 2; i2++) {
                int idx = tid + i2*256;
                int kp = idx >> 5, c = (idx & 31) * 4;
                cpa(&S[10240 + st*4352 + kp*STRB + c], Wh + (size_t)(kc*16 + kp)*256 + n0 + c);
                cpa(&S[12416 + st*4352 + kp*STRB + c], Wl + (size_t)(kc*16 + kp)*256 + n0 + c);
            }
            CP_COMMIT();
        }
        const uint32_t* AH = S + (it&1)*5120;
        const uint32_t* AL = AH + 2560;
        const uint32_t* BH = S + 10240 + (it&1)*4352;
        const uint32_t* BL = BH + 2176;
#pragma unroll
        for (int kb = 0; kb < 16; kb += 8) {
            uint32_t ah[2][4], al[2][4];
#pragma unroll
            for (int mi=0;mi<2;mi++) {
                int rb = wm*32 + mi*16;
                ah[mi][0] = AH[(rb+g  )*STRA + kb+t  ]; al[mi][0] = AL[(rb+g  )*STRA + kb+t  ];
                ah[mi][1] = AH[(rb+g+8)*STRA + kb+t  ]; al[mi][1] = AL[(rb+g+8)*STRA + kb+t  ];
                ah[mi][2] = AH[(rb+g  )*STRA + kb+t+4]; al[mi][2] = AL[(rb+g  )*STRA + kb+t+4];
                ah[mi][3] = AH[(rb+g+8)*STRA + kb+t+4]; al[mi][3] = AL[(rb+g+8)*STRA + kb+t+4];
            }
#pragma unroll
            for (int ni=0;ni<8;ni++) {
                int cb = wn*64 + ni*8 + g;
                uint32_t bh[2], bl[2];
                bh[0] = BH[(kb+t  )*STRB + cb]; bl[0] = BL[(kb+t  )*STRB + cb];
                bh[1] = BH[(kb+t+4)*STRB + cb]; bl[1] = BL[(kb+t+4)*STRB + cb];
#pragma unroll
                for (int mi=0;mi<2;mi++) {
                    mma16(acc[mi][ni], ah[mi], bh);
                    mma16(acc[mi][ni], ah[mi], bl);
                    mma16(acc[mi][ni], al[mi], bh);
                }
            }
        }
    }
    // epilogue: (acc + bias) * dinv -> smem staging -> packed kpairN global
    __syncthreads();
    float* stg = (float*)S;   // 128 x 132 floats
#pragma unroll
    for (int mi=0;mi<2;mi++) {
        int r0 = wm*32 + mi*16 + g, r1 = r0 + 8;
        float d0 = sDv[r0], d1 = sDv[r1];
#pragma unroll
        for (int ni=0;ni<8;ni++) {
            int c0 = wn*64 + ni*8 + 2*t;
            float b0 = bias[n0 + c0], b1 = bias[n0 + c0 + 1];
            *(float2*)&stg[r0*132 + c0] = make_float2((acc[mi][ni][0]+b0)*d0, (acc[mi][ni][1]+b1)*d0);
            *(float2*)&stg[r1*132 + c0] = make_float2((acc[mi][ni][2]+b0)*d1, (acc[mi][ni][3]+b1)*d1);
        }
    }
    __syncthreads();
#pragma unroll
    for (int i2 = 0; i2 < 8; i2++) {
        int idx = tid + i2*256;
        int kp = idx >> 5, c = (idx & 31) * 4;
        float4 u = *(float4*)&stg[(2*kp  )*132 + c];
        float4 v = *(float4*)&stg[(2*kp+1)*132 + c];
        uint4 H, L;
        split2(u.x, v.x, H.x, L.x);
        split2(u.y, v.y, H.y, L.y);
        split2(u.z, v.z, H.z, L.z);
        split2(u.w, v.w, H.w, L.w);
        *(uint4*)&g_XWh[((size_t)(m0>>1) + kp)*256 + n0 + c] = H;
        *(uint4*)&g_XWl[((size_t)(m0>>1) + kp)*256 + n0 + c] = L;
    }
}

// ---------------- H = dinv_i * A(bn) @ XWs  + fused BN stats -> g_Hb ----------------
__global__ void __launch_bounds__(256) k_bmm() {
    extern __shared__ uint32_t S[];   // 18944 words
    __shared__ float sDv[128];
    __shared__ float sSum[128], sSq[128];
    int bn = blockIdx.y;
    int b = bn >> 2, n = bn & 3;
    int h0 = blockIdx.x * 128;
    int rowbase = b*TP + n*PP;
    int tid = threadIdx.x, w = tid >> 5, lane = tid & 31, g = lane >> 2, t = lane & 3;
    int wm = w & 3, wn = w >> 2;
    if (tid < 128) { sDv[tid] = g_dinv[rowbase + tid]; sSum[tid] = 0.f; sSq[tid] = 0.f; }

    float acc[2][8][4];
#pragma unroll
    for (int mi=0;mi<2;mi++)
#pragma unroll
        for (int ni=0;ni<8;ni++)
#pragma unroll
            for (int q=0;q<4;q++) acc[mi][ni][q] = 0.f;

    {
        int kc = 0;
#pragma unroll
        for (int i2 = 0; i2 < 2; i2++) {
            int idx = tid + i2*256;
            int r = idx >> 2, q = (idx & 3) * 4;
            cpa(&S[r*STRA + q],        g_Ah + ((size_t)bn*128 + r)*64 + kc*16 + q);
            cpa(&S[2560 + r*STRA + q], g_Al + ((size_t)bn*128 + r)*64 + kc*16 + q);
        }
#pragma unroll
        for (int i2 = 0; i2 < 2; i2++) {
            int idx = tid + i2*256;
            int kp = idx >> 5, c = (idx & 31) * 4;
            cpa(&S[10240 + kp*STRB + c], g_XWh + ((size_t)(rowbase>>1) + kc*16 + kp)*256 + h0 + c);
            cpa(&S[12416 + kp*STRB + c], g_XWl + ((size_t)(rowbase>>1) + kc*16 + kp)*256 + h0 + c);
        }
        CP_COMMIT();
    }
    for (int it = 0; it < 4; it++) {
        CP_WAIT0();
        __syncthreads();
        if (it + 1 < 4) {
            int st = (it+1) & 1, kc = it+1;
#pragma unroll
            for (int i2 = 0; i2 < 2; i2++) {
                int idx = tid + i2*256;
                int r = idx >> 2, q = (idx & 3) * 4;
                cpa(&S[st*5120 + r*STRA + q],        g_Ah + ((size_t)bn*128 + r)*64 + kc*16 + q);
                cpa(&S[st*5120 + 2560 + r*STRA + q], g_Al + ((size_t)bn*128 + r)*64 + kc*16 + q);
            }
#pragma unroll
            for (int i2 = 0; i2 < 2; i2++) {
                int idx = tid + i2*256;
                int kp = idx >> 5, c = (idx & 31) * 4;
                cpa(&S[10240 + st*4352 + kp*STRB + c], g_XWh + ((size_t)(rowbase>>1) + kc*16 + kp)*256 + h0 + c);
                cpa(&S[12416 + st*4352 + kp*STRB + c], g_XWl + ((size_t)(rowbase>>1) + kc*16 + kp)*256 + h0 + c);
            }
            CP_COMMIT();
        }
        const uint32_t* AH = S + (it&1)*5120;
        const uint32_t* AL = AH + 2560;
        const uint32_t* BH = S + 10240 + (it&1)*4352;
        const uint32_t* BL = BH + 2176;
#pragma unroll
        for (int kb = 0; kb < 16; kb += 8) {
            uint32_t ah[2][4], al[2][4];
#pragma unroll
            for (int mi=0;mi<2;mi++) {
                int rb = wm*32 + mi*16;
                ah[mi][0] = AH[(rb+g  )*STRA + kb+t  ]; al[mi][0] = AL[(rb+g  )*STRA + kb+t  ];
                ah[mi][1] = AH[(rb+g+8)*STRA + kb+t  ]; al[mi][1] = AL[(rb+g+8)*STRA + kb+t  ];
                ah[mi][2] = AH[(rb+g  )*STRA + kb+t+4]; al[mi][2] = AL[(rb+g  )*STRA + kb+t+4];
                ah[mi][3] = AH[(rb+g+8)*STRA + kb+t+4]; al[mi][3] = AL[(rb+g+8)*STRA + kb+t+4];
            }
#pragma unroll
            for (int ni=0;ni<8;ni++) {
                int cb = wn*64 + ni*8 + g;
                uint32_t bh[2], bl[2];
                bh[0] = BH[(kb+t  )*STRB + cb]; bl[0] = BL[(kb+t  )*STRB + cb];
                bh[1] = BH[(kb+t+4)*STRB + cb]; bl[1] = BL[(kb+t+4)*STRB + cb];
#pragma unroll
                for (int mi=0;mi<2;mi++) {
                    mma16(acc[mi][ni], ah[mi], bh);
                    mma16(acc[mi][ni], ah[mi], bl);
                    mma16(acc[mi][ni], al[mi], bh);
                }
            }
        }
    }
    float* base = g_Hb + (size_t)rowbase * HH;
#pragma unroll
    for (int ni=0;ni<8;ni++) {
        int cl = wn*64 + ni*8 + 2*t;
        float cs0 = 0.f, cs1 = 0.f, cq0 = 0.f, cq1 = 0.f;
#pragma unroll
        for (int mi=0;mi<2;mi++) {
            int r0 = wm*32 + mi*16 + g, r1 = r0 + 8;
            float d0 = sDv[r0], d1 = sDv[r1];
            float v00 = acc[mi][ni][0]*d0, v01 = acc[mi][ni][1]*d0;
            float v10 = acc[mi][ni][2]*d1, v11 = acc[mi][ni][3]*d1;
            *(float2*)&base[(size_t)r0*HH + h0 + cl] = make_float2(v00, v01);
            *(float2*)&base[(size_t)r1*HH + h0 + cl] = make_float2(v10, v11);
            cs0 += v00 + v10; cs1 += v01 + v11;
            cq0 += v00*v00 + v10*v10; cq1 += v01*v01 + v11*v11;
        }
        atomicAdd(&sSum[cl],   cs0);
        atomicAdd(&sSum[cl+1], cs1);
        atomicAdd(&sSq[cl],    cq0);
        atomicAdd(&sSq[cl+1],  cq1);
    }
    __syncthreads();
    if (tid < 128) {
        atomicAdd(&g_sum[h0 + tid],   sSum[tid]);
        atomicAdd(&g_sumsq[h0 + tid], sSq[tid]);
    }
}

// ---------------- BN finalize (re-zeros accumulators) ----------------
__global__ void k_bnfin(const float* __restrict__ g, const float* __restrict__ be) {
    int c = threadIdx.x;
    const float invn = 1.0f / (float)NROWS;
    float m = g_sum[c] * invn;
    float v = g_sumsq[c] * invn - m*m;
    float sc = g[c] * rsqrtf(v + 1e-5f);
    g_scale[c] = sc;
    g_shift[c] = be[c] - m*sc;
    g_sum[c] = 0.f;
    g_sumsq[c] = 0.f;
}

// ---------------- split-K readout GEMM: [64,131072] @ [131072,128] ----------------
// A-side: g_Hbh/l (post-BN packed, pure copy). B-side: Wm1 fp32 staged + split.
__global__ void __launch_bounds__(256) k_mlp1(const float* __restrict__ Wm1) {
    extern __shared__ uint32_t S[];   // 17920 words
    // offsets: AH0=0(1280) AL0=1280 AH1=2560 AL1=3840 BRAW0=5120(4224) BRAW1=9344 BHs=13568(2176) BLs=15744
    int kc0 = blockIdx.x;             // 0..255
    int kbase = kc0 * 512;
    int tid = threadIdx.x, w = tid >> 5, lane = tid & 31, g = lane >> 2, t = lane & 3;
    int wm = w & 3, wn = w >> 2;
    float acc[8][4];
#pragma unroll
    for (int ni=0;ni<8;ni++)
#pragma unroll
        for (int q=0;q<4;q++) acc[ni][q] = 0.f;

    {
        int kb0 = kbase;   // chunk 0
        {
            int r = tid >> 2, q = (tid & 3) * 4;
            cpa(&S[r*STRA + q],        g_Hbh + (size_t)r*(FEAT/2) + (kb0>>1) + q);
            cpa(&S[1280 + r*STRA + q], g_Hbl + (size_t)r*(FEAT/2) + (kb0>>1) + q);
        }
#pragma unroll
        for (int i2 = 0; i2 < 4; i2++) {
            int idx = tid + i2*256;
            int rr = idx >> 5, c = (idx & 31) * 4;
            cpa(&S[5120 + rr*132 + c], Wm1 + (size_t)(kb0 + rr)*128 + c);
        }
        CP_COMMIT();
    }
    for (int it = 0; it < 16; it++) {
        CP_WAIT0();
        __syncthreads();
        if (it + 1 < 16) {
            int st = (it+1) & 1;
            int kb0 = kbase + (it+1)*32;
            {
                int r = tid >> 2, q = (tid & 3) * 4;
                cpa(&S[st*2560 + r*STRA + q],        g_Hbh + (size_t)r*(FEAT/2) + (kb0>>1) + q);
                cpa(&S[st*2560 + 1280 + r*STRA + q], g_Hbl + (size_t)r*(FEAT/2) + (kb0>>1) + q);
            }
#pragma unroll
            for (int i2 = 0; i2 < 4; i2++) {
                int idx = tid + i2*256;
                int rr = idx >> 5, c = (idx & 31) * 4;
                cpa(&S[5120 + st*4224 + rr*132 + c], Wm1 + (size_t)(kb0 + rr)*128 + c);
            }
            CP_COMMIT();
        }
        // split Wm1 raw -> BHs/BLs
        const float* braw = (const float*)(S + 5120 + (it&1)*4224);
#pragma unroll
        for (int i2 = 0; i2 < 2; i2++) {
            int idx = tid + i2*256;
            int kp = idx >> 5, c = (idx & 31) * 4;
            float4 u = *(const float4*)&braw[(2*kp  )*132 + c];
            float4 v = *(const float4*)&braw[(2*kp+1)*132 + c];
            uint4 H, L;
            split2(u.x, v.x, H.x, L.x);
            split2(u.y, v.y, H.y, L.y);
            split2(u.z, v.z, H.z, L.z);
            split2(u.w, v.w, H.w, L.w);
            *(uint4*)&S[13568 + kp*STRB + c] = H;
            *(uint4*)&S[15744 + kp*STRB + c] = L;
        }
        __syncthreads();
        const uint32_t* AH = S + (it&1)*2560;
        const uint32_t* AL = AH + 1280;
        const uint32_t* BH = S + 13568;
        const uint32_t* BL = S + 15744;
#pragma unroll
        for (int kb = 0; kb < 16; kb += 8) {
            uint32_t ah[4], al[4];
            int rb = wm*16;
            ah[0] = AH[(rb+g  )*STRA + kb+t  ]; al[0] = AL[(rb+g  )*STRA + kb+t  ];
            ah[1] = AH[(rb+g+8)*STRA + kb+t  ]; al[1] = AL[(rb+g+8)*STRA + kb+t  ];
            ah[2] = AH[(rb+g  )*STRA + kb+t+4]; al[2] = AL[(rb+g  )*STRA + kb+t+4];
            ah[3] = AH[(rb+g+8)*STRA + kb+t+4]; al[3] = AL[(rb+g+8)*STRA + kb+t+4];
#pragma unroll
            for (int ni=0;ni<8;ni++) {
                int cb = wn*64 + ni*8 + g;
                uint32_t bh[2], bl[2];
                bh[0] = BH[(kb+t  )*STRB + cb]; bl[0] = BL[(kb+t  )*STRB + cb];
                bh[1] = BH[(kb+t+4)*STRB + cb]; bl[1] = BL[(kb+t+4)*STRB + cb];
                mma16(acc[ni], ah, bh);
                mma16(acc[ni], ah, bl);
                mma16(acc[ni], al, bh);
            }
        }
    }
    float* out = g_Z1part + (size_t)kc0 * (B*M1);
    int r0 = wm*16 + g, r1 = r0 + 8;
#pragma unroll
    for (int ni=0;ni<8;ni++) {
        int c0 = wn*64 + ni*8 + 2*t;
        *(float2*)&out[r0*M1 + c0] = make_float2(acc[ni][0], acc[ni][1]);
        *(float2*)&out[r1*M1 + c0] = make_float2(acc[ni][2], acc[ni][3]);
    }
}

__global__ void k_red(const float* __restrict__ bm1) {
    int o = blockIdx.x*256 + threadIdx.x;   // 0..8191
    float s = bm1[o & 127];
    for (int kc = 0; kc < KCHUNKS; kc++) s += g_Z1part[(size_t)kc*(B*M1) + o];
    g_z1[o] = s;
}

// ---------------- head (exact fp32) ----------------
__global__ void __launch_bounds__(256) k_head(const float* __restrict__ gm1, const float* __restrict__ bem1,
                                              const float* __restrict__ Wm2, const float* __restrict__ bm2,
                                              const float* __restrict__ gm2, const float* __restrict__ bem2,
                                              const float* __restrict__ Wm3, const float* __restrict__ bm3,
                                              float* __restrict__ out) {
    __shared__ float sz1[64][128];
    __shared__ float sz2[64][64];
    int tid = threadIdx.x;

    if (tid < 128) {
        float s = 0.f, s2 = 0.f;
        for (int b = 0; b < 64; b++) { float v = g_z1[b*128 + tid]; s += v; s2 += v*v; }
        float m = s * (1.f/64.f), var = s2 * (1.f/64.f) - m*m;
        float sc = gm1[tid] * rsqrtf(var + 1e-5f);
        float sh = bem1[tid] - m*sc;
        for (int b = 0; b < 64; b++)
            sz1[b][tid] = fmaxf(fmaf(g_z1[b*128 + tid], sc, sh), 0.f);
    }
    __syncthreads();

    for (int o = tid; o < 4096; o += 256) {
        int b = o >> 6, j = o & 63;
        float s = bm2[j];
#pragma unroll 8
        for (int m = 0; m < 128; m++) s = fmaf(sz1[b][m], Wm2[m*64 + j], s);
        sz2[b][j] = s;
    }
    __syncthreads();

    if (tid < 64) {
        float s = 0.f, s2 = 0.f;
        for (int b = 0; b < 64; b++) { float v = sz2[b][tid]; s += v; s2 += v*v; }
        float m = s * (1.f/64.f), var = s2 * (1.f/64.f) - m*m;
        float sc = gm2[tid] * rsqrtf(var + 1e-5f);
        float sh = bem2[tid] - m*sc;
        for (int b = 0; b < 64; b++)
            sz2[b][tid] = fmaxf(fmaf(sz2[b][tid], sc, sh), 0.f);
    }
    __syncthreads();

    if (tid < 128) {
        int b = tid >> 1, c = tid & 1;
        float s = bm3[c];
#pragma unroll
        for (int j = 0; j < 64; j++) s = fmaf(sz2[b][j], Wm3[j*2 + c], s);
        out[b*2 + c] = s;
    }
}

// ---------------- launch ----------------
extern "C" void kernel_launch(void* const* d_in, const int* in_sizes, int n_in,
                              void* d_out, int out_size) {
    const float* x    = (const float*)d_in[0];
    const float* mask = (const float*)d_in[1];
    const float* W1   = (const float*)d_in[2];
    const float* b1   = (const float*)d_in[3];
    const float* g1   = (const float*)d_in[4];
    const float* be1  = (const float*)d_in[5];
    const float* W2   = (const float*)d_in[6];
    const float* b2   = (const float*)d_in[7];
    const float* g2   = (const float*)d_in[8];
    const float* be2  = (const float*)d_in[9];
    const float* Wm1  = (const float*)d_in[10];
    const float* bm1  = (const float*)d_in[11];
    const float* gm1  = (const float*)d_in[12];
    const float* bem1 = (const float*)d_in[13];
    const float* Wm2  = (const float*)d_in[14];
    const float* bm2  = (const float*)d_in[15];
    const float* gm2  = (const float*)d_in[16];
    const float* bem2 = (const float*)d_in[17];
    const float* Wm3  = (const float*)d_in[18];
    const float* bm3  = (const float*)d_in[19];
    float* out = (float*)d_out;

    static bool init = false;
    static uint32_t *pXh, *pXl, *pHh, *pHl, *pW1h, *pW1l, *pW2h, *pW2l;
    if (!init) {
        init = true;
        cudaFuncSetAttribute(k_xw,   cudaFuncAttributeMaxDynamicSharedMemorySize, 18944*4);
        cudaFuncSetAttribute(k_bmm,  cudaFuncAttributeMaxDynamicSharedMemorySize, 18944*4);
        cudaFuncSetAttribute(k_mlp1, cudaFuncAttributeMaxDynamicSharedMemorySize, 17920*4);
        cudaGetSymbolAddress((void**)&pXh,  g_Xh);
        cudaGetSymbolAddress((void**)&pXl,  g_Xl);
        cudaGetSymbolAddress((void**)&pHh,  g_Hbh);
        cudaGetSymbolAddress((void**)&pHl,  g_Hbl);
        cudaGetSymbolAddress((void**)&pW1h, g_W1h);
        cudaGetSymbolAddress((void**)&pW1l, g_W1l);
        cudaGetSymbolAddress((void**)&pW2h, g_W2h);
        cudaGetSymbolAddress((void**)&pW2l, g_W2l);
    }

    // prep: norms, splits
    k_invn<<<NROWS/8, 256>>>(x);
    k_splitX<<<(int)((size_t)NROWS*DD/4/256), 256>>>(x);
    k_splitW<<<32, 256>>>(W1, pW1h, pW1l);
    k_splitW<<<32, 256>>>(W2, pW2h, pW2l);
    k_simA<<<B*NSUB, 256>>>(mask);

    // ---- GCN layer 1 ----
    k_xw<<<dim3(2, 256), 256, 18944*4>>>(pXh, pXl, pW1h, pW1l, b1);
    k_bmm<<<dim3(2, 256), 256, 18944*4>>>();
    k_bnfin<<<1, 256>>>(g1, be1);
    k_bnsplit<<<(int)((size_t)NROWS*HH/4/256), 256>>>();

    // ---- GCN layer 2 ----
    k_xw<<<dim3(2, 256), 256, 18944*4>>>(pHh, pHl, pW2h, pW2l, b2);
    k_bmm<<<dim3(2, 256), 256, 18944*4>>>();
    k_bnfin<<<1, 256>>>(g2, be2);
    k_bnsplit<<<(int)((size_t)NROWS*HH/4/256), 256>>>();

    // ---- readout + head ----
    k_mlp1<<<KCHUNKS, 256, 17920*4>>>(Wm1);
    k_red<<<32, 256>>>(bm1);
    k_head<<<1, 256>>>(gm1, bem1, Wm2, bm2, gm2, bem2, Wm3, bm3, out);
}